// round 15
// baseline (speedup 1.0000x reference)
#include <cuda_runtime.h>
#include <cstdint>

#define Tlen 1024
#define NCTA 128
#define NTHR 512

typedef unsigned long long ull;

#define TX1H 1024  // per dest CTA per step per h1-half: 64 dims x 4 batches x 4B
#define TX2  1024  // h2: 64 dims x 4 batches x 4B

struct __align__(16) Smem {
    ull   mb1h[4][2];      // h1 tx-barriers [buf][half]   (64 B)
    ull   mb2[4];          // h2 tx-barriers [buf]         (32 B) -> hc at 96 B
    alignas(16) float hc[4][4][192];  // [buf][batch][h1 perm (0..127) ++ h2]
    float xs[1024][4];     // staged x, interleaved [t][b]
};
__shared__ Smem sm;

__device__ __forceinline__ float tanha(float x) {
    float y; asm("tanh.approx.f32 %0, %1;" : "=f"(y) : "f"(x)); return y;
}
__device__ __forceinline__ float sigm(float v) { return fmaf(tanha(0.5f * v), 0.5f, 0.5f); }

__device__ __forceinline__ uint32_t s2u(const void* p) {
    uint32_t a;
    asm("{ .reg .u64 t; cvta.to.shared.u64 t, %1; cvt.u32.u64 %0, t; }" : "=r"(a) : "l"(p));
    return a;
}
__device__ __forceinline__ uint32_t mapa_r(uint32_t saddr, int rank) {
    uint32_t r;
    asm volatile("mapa.shared::cluster.u32 %0, %1, %2;" : "=r"(r) : "r"(saddr), "r"(rank));
    return r;
}
__device__ __forceinline__ void st_async(uint32_t addr, float v, uint32_t mbar) {
    asm volatile(
        "st.async.shared::cluster.mbarrier::complete_tx::bytes.b32 [%0], %1, [%2];"
        :: "r"(addr), "r"(__float_as_uint(v)), "r"(mbar) : "memory");
}
__device__ __forceinline__ void arm_tx(uint32_t mbar, uint32_t bytes) {
    asm volatile("mbarrier.arrive.expect_tx.shared.b64 _, [%0], %1;"
                 :: "r"(mbar), "r"(bytes) : "memory");
}
__device__ __forceinline__ void mwait(uint32_t mbar, uint32_t parity) {
    asm volatile(
        "{\n\t.reg .pred P1;\n\t"
        "WAIT_LOOP_%=:\n\t"
        "mbarrier.try_wait.parity.acquire.cta.shared::cta.b64 P1, [%0], %1, 0x989680;\n\t"
        "@P1 bra.uni WAIT_DONE_%=;\n\t"
        "bra.uni WAIT_LOOP_%=;\n\t"
        "WAIT_DONE_%=:\n\t}"
        :: "r"(mbar), "r"(parity) : "memory");
}
__device__ __forceinline__ void csync() {
    asm volatile("barrier.cluster.arrive.aligned;" ::: "memory");
    asm volatile("barrier.cluster.wait.aligned;" ::: "memory");
}
__device__ __forceinline__ void ffma2(ull& acc, ull a, ull b) {
    asm("fma.rn.f32x2 %0, %1, %2, %0;" : "+l"(acc) : "l"(a), "l"(b));
}
__device__ __forceinline__ float2 u2f2(ull u) {
    float2 f;
    asm("mov.b64 {%0, %1}, %2;" : "=f"(f.x), "=f"(f.y) : "l"(u));
    return f;
}
__device__ __forceinline__ ull pk(float lo, float hi) {
    ull r;
    asm("mov.b64 %0, {%1, %2};" : "=l"(r) : "f"(lo), "f"(hi));
    return r;
}

// 4x4 gate<->batch transpose across lane bits [0:1]; lane G: in s[b]=M[G][b],
// out s[j]=M[j][G].
__device__ __forceinline__ void transpose4(float s[4], int G) {
    const unsigned FULL = 0xffffffffu;
    int g0 = G & 1, g1 = (G >> 1) & 1;
    float x0 = g0 ? s[0] : s[1];
    float x1 = g0 ? s[2] : s[3];
    float y0 = __shfl_xor_sync(FULL, x0, 1);
    float y1 = __shfl_xor_sync(FULL, x1, 1);
    if (g0) { s[0] = y0; s[2] = y1; } else { s[1] = y0; s[3] = y1; }
    x0 = g1 ? s[0] : s[2];
    x1 = g1 ? s[1] : s[3];
    y0 = __shfl_xor_sync(FULL, x0, 2);
    y1 = __shfl_xor_sync(FULL, x1, 2);
    if (g1) { s[0] = y0; s[1] = y1; } else { s[2] = y0; s[3] = y1; }
}

#define HC_BUF_BYTES (4 * 192 * 4)

__global__ void __launch_bounds__(NTHR, 1) __cluster_dims__(4, 1, 1)
lstm_cluster_kernel(
    const float* __restrict__ x,
    const float* __restrict__ w_ih1,  // [512][1]
    const float* __restrict__ w_hh1,  // [512][128]
    const float* __restrict__ b_ih1,
    const float* __restrict__ b_hh1,
    const float* __restrict__ w_ih2,  // [256][128]
    const float* __restrict__ w_hh2,  // [256][64]
    const float* __restrict__ b_ih2,
    const float* __restrict__ b_hh2,
    float* __restrict__ out)          // [128][64]
{
    const int tid  = threadIdx.x;
    const int lane = tid & 31;
    const int wrp  = tid >> 5;        // 16 warps: 0-7 = L1, 8-15 = L2
    const int q    = blockIdx.x & 3;
    const int cid  = blockIdx.x >> 2;
    const int g    = lane & 3;        // gate (batch after transpose)

    // ---------------- init smem ----------------
    for (int idx = tid; idx < 4 * 1024; idx += NTHR) {
        int b = idx >> 10, t = idx & 1023;
        sm.xs[t][b] = x[(4 * cid + b) * 1024 + t];
    }
    for (int idx = tid; idx < 4 * 4 * 192; idx += NTHR)
        (&sm.hc[0][0][0])[idx] = 0.0f;
    if (tid == 0) {
#pragma unroll
        for (int j = 0; j < 4; j++) {
            uint32_t alo = s2u(&sm.mb1h[j][0]);
            uint32_t ahi = s2u(&sm.mb1h[j][1]);
            uint32_t a2  = s2u(&sm.mb2[j]);
            asm volatile("mbarrier.init.shared.b64 [%0], 1;" :: "r"(alo) : "memory");
            asm volatile("mbarrier.init.shared.b64 [%0], 1;" :: "r"(ahi) : "memory");
            asm volatile("mbarrier.init.shared.b64 [%0], 1;" :: "r"(a2) : "memory");
            arm_tx(alo, TX1H);
            arm_tx(ahi, TX1H);
            arm_tx(a2, TX2);
        }
    }

    // ---------------- cluster address constants ----------------
    const uint32_t base0 = s2u(&sm);
    const uint32_t m0    = mapa_r(base0, 0);
    uint32_t dd[4];
    dd[0] = 0;
    dd[1] = mapa_r(base0, 1) - m0;
    dd[2] = mapa_r(base0, 2) - m0;
    dd[3] = mapa_r(base0, 3) - m0;
    const uint32_t HCO  = s2u(&sm.hc[0][0][0]) - base0;
    const uint32_t MB1O = s2u(&sm.mb1h[0][0]) - base0;  // [buf][half]: buf*16 + half*8
    const uint32_t MB2O = s2u(&sm.mb2[0]) - base0;

    csync();  // armed mbars + zeroed smem + xs visible cluster-wide

    const unsigned FULL = 0xffffffffu;

    if (wrp < 8) {
        // ================= L1 warps: steps 0..Tlen-1 =================
        // lane = g(2b) | kq(2b) | dlb(1b); rows (g,dl),(g,dl+16); logical k-slice
        // [kq*32, kq*32+32) stored at physical floats {kq*4 + 16j + e}.
        const int kq  = (lane >> 2) & 3;
        const int dlb = (lane >> 4) & 1;
        const int dl  = wrp * 2 + dlb;        // 0..15
        const int rsel = (kq >= 2);
        const int myhalf = kq >> 1;           // consumes source CTA kq -> half kq>>1
        ull w1a[16], w1b[16];
        {
            const int ra = g * 128 + 32 * q + dl;
            const float* pa = w_hh1 + ra * 128 + kq * 32;
            const float* pb = w_hh1 + (ra + 16) * 128 + kq * 32;
#pragma unroll
            for (int j = 0; j < 8; j++) {
                float4 fa = *reinterpret_cast<const float4*>(pa + j * 4);
                float4 fb = *reinterpret_cast<const float4*>(pb + j * 4);
                w1a[2 * j] = pk(fa.x, fa.y); w1a[2 * j + 1] = pk(fa.z, fa.w);
                w1b[2 * j] = pk(fb.x, fb.y); w1b[2 * j + 1] = pk(fb.z, fb.w);
            }
        }
        float wih1s[4], b1s[4];
#pragma unroll
        for (int j = 0; j < 4; j++) {
            int r = j * 128 + 32 * q + dl + (rsel ? 16 : 0);
            wih1s[j] = w_ih1[r];
            b1s[j]   = b_ih1[r] + b_hh1[r];
        }
        const int dv = dl + (rsel ? 16 : 0);
        // producer store slot: physical permutation of global dim D = 32q + dv
        const int p1 = (dv >> 2) * 16 + q * 4 + (dv & 3);
        const int prodhalf = q >> 1;          // this CTA's data belongs to half q>>1
        const int rep = kq & 1;               // replica -> ranks {2rep, 2rep+1}
        const uint32_t rA = m0 + dd[2 * rep];
        const uint32_t rB = m0 + dd[2 * rep + 1];

        float c1 = 0.0f;
        for (int i = 0; i < Tlen; i++) {
            if (i >= 4) {                     // ring safety FIRST (always complete)
                const int s = i - 3;
                mwait(base0 + MB2O + (s & 3) * 8, (uint32_t)((s >> 2) & 1));
            }
            int bufR = 3;                     // zeroed buffer for i==0
            if (i >= 1) {
                const int s = i - 1;
                bufR = s & 3;
                const uint32_t par = (uint32_t)((s >> 2) & 1);
                mwait(base0 + MB1O + bufR * 16 + myhalf * 8, par);  // own half only
                if (wrp == 0 && (lane == 0 || lane == 8))  // lane0->lo, lane8->hi
                    arm_tx(base0 + MB1O + bufR * 16 + myhalf * 8, TX1H);
            }
            float s0[4], s1[4];
#pragma unroll
            for (int b = 0; b < 4; b++) {
                const ulonglong2* hp =
                    reinterpret_cast<const ulonglong2*>(&sm.hc[bufR][b][0]);
                ull a0 = 0ull, a1 = 0ull, b0 = 0ull, b1 = 0ull;
#pragma unroll
                for (int j = 0; j < 8; j++) {
                    ulonglong2 h = hp[kq + 4 * j];   // physical: 4 distinct addrs
                    ffma2(a0, h.x, w1a[2 * j]);
                    ffma2(a1, h.y, w1a[2 * j + 1]);
                    ffma2(b0, h.x, w1b[2 * j]);
                    ffma2(b1, h.y, w1b[2 * j + 1]);
                }
                float2 f0 = u2f2(a0), f1 = u2f2(a1);
                float2 f2 = u2f2(b0), f3 = u2f2(b1);
                s0[b] = (f0.x + f0.y) + (f1.x + f1.y);
                s1[b] = (f2.x + f2.y) + (f3.x + f3.y);
            }
#pragma unroll
            for (int b = 0; b < 4; b++) {
                s0[b] += __shfl_xor_sync(FULL, s0[b], 4);
                s1[b] += __shfl_xor_sync(FULL, s1[b], 4);
                s0[b] += __shfl_xor_sync(FULL, s0[b], 8);
                s1[b] += __shfl_xor_sync(FULL, s1[b], 8);
            }
            float sel[4];
#pragma unroll
            for (int b = 0; b < 4; b++) sel[b] = rsel ? s1[b] : s0[b];
            transpose4(sel, g);
            const int beta = g;
            float xv = sm.xs[i][beta];
            float ai = fmaf(xv, wih1s[0], sel[0] + b1s[0]);
            float af = fmaf(xv, wih1s[1], sel[1] + b1s[1]);
            float ag = fmaf(xv, wih1s[2], sel[2] + b1s[2]);
            float ao = fmaf(xv, wih1s[3], sel[3] + b1s[3]);
            c1 = sigm(af) * c1 + sigm(ai) * tanha(ag);
            float h = sigm(ao) * tanha(c1);
            const int bufW = i & 3;
            uint32_t off  = HCO + bufW * HC_BUF_BYTES + (beta * 192 + p1) * 4;
            uint32_t mbof = MB1O + bufW * 16 + prodhalf * 8;
            st_async(rA + off, h, rA + mbof);
            st_async(rB + off, h, rB + mbof);
        }
    } else {
        // ================= L2 warps: steps 0..Tlen =================
        // lane = g(2b) | ke(3b); rows (g,dl2),(g,dl2+8).
        // h1-part: physical floats {ke*4 + 32j + e}, j=0..3 -> logical
        //          k = (ke&3)*32 + (ke>>2)*4 + 8j + e   (source CTA = ke&3)
        // h2-part: floats {128 + ke*4 + 32(j-4) + e}, j=4,5 (unpermuted)
        const int ke  = lane >> 2;            // 0..7
        const int dl2 = wrp - 8;              // 0..7
        const int rsel = (ke >= 4);
        const int myhalf = (ke >> 1) & 1;     // source CTA ke&3 -> half (ke&3)>>1
        ull w2a[12], w2b[12];
        {
            const int ra = g * 64 + 16 * q + dl2;
            const int rb = ra + 8;
#pragma unroll
            for (int j = 0; j < 6; j++) {
                float4 fa, fb;
                if (j < 4) {
                    int k0 = (ke & 3) * 32 + (ke >> 2) * 4 + 8 * j;  // 4-aligned
                    fa = *reinterpret_cast<const float4*>(w_ih2 + ra * 128 + k0);
                    fb = *reinterpret_cast<const float4*>(w_ih2 + rb * 128 + k0);
                } else {
                    int k0 = ke * 4 + 32 * (j - 4);                  // h2 part
                    fa = *reinterpret_cast<const float4*>(w_hh2 + ra * 64 + k0);
                    fb = *reinterpret_cast<const float4*>(w_hh2 + rb * 64 + k0);
                }
                w2a[2 * j] = pk(fa.x, fa.y); w2a[2 * j + 1] = pk(fa.z, fa.w);
                w2b[2 * j] = pk(fb.x, fb.y); w2b[2 * j + 1] = pk(fb.z, fb.w);
            }
        }
        float b2s[4];
#pragma unroll
        for (int j = 0; j < 4; j++) {
            int r = j * 64 + 16 * q + dl2 + (rsel ? 8 : 0);
            b2s[j] = b_ih2[r] + b_hh2[r];
        }
        const int dv2 = dl2 + (rsel ? 8 : 0);
        const uint32_t rQ = m0 + dd[ke & 3];  // 1 store/lane covers 4 ranks/row

        float c2 = 0.0f;
        for (int i = 0; i <= Tlen; i++) {
            float h2v = 0.0f;
            if (i >= 1) {
                const int s = i - 1;
                const int bufR = s & 3;
                const uint32_t par = (uint32_t)((s >> 2) & 1);
                // 1) old h2 first (almost always complete)
                mwait(base0 + MB2O + bufR * 8, par);
                if (tid == 256)
                    arm_tx(base0 + MB2O + bufR * 8, TX2);
                const ulonglong2* hp0 =
                    reinterpret_cast<const ulonglong2*>(&sm.hc[bufR][0][0]);
                // 2) h2-part dot (j=4,5) while h1 may still be in flight
                ull a0[4], a1[4], b0[4], b1[4];
#pragma unroll
                for (int b = 0; b < 4; b++) {
                    const ulonglong2* hp = hp0 + b * 48;   // 192 floats = 48 ull2
                    a0[b] = a1[b] = b0[b] = b1[b] = 0ull;
#pragma unroll
                    for (int j = 4; j < 6; j++) {
                        ulonglong2 h = hp[ke + 8 * j];
                        ffma2(a0[b], h.x, w2a[2 * j]);
                        ffma2(a1[b], h.y, w2a[2 * j + 1]);
                        ffma2(b0[b], h.x, w2b[2 * j]);
                        ffma2(b1[b], h.y, w2b[2 * j + 1]);
                    }
                }
                // 3) fresh h1: wait only own half, then h1-part dot
                mwait(base0 + MB1O + bufR * 16 + myhalf * 8, par);
                float s0[4], s1[4];
#pragma unroll
                for (int b = 0; b < 4; b++) {
                    const ulonglong2* hp = hp0 + b * 48;
#pragma unroll
                    for (int j = 0; j < 4; j++) {
                        ulonglong2 h = hp[ke + 8 * j];
                        ffma2(a0[b], h.x, w2a[2 * j]);
                        ffma2(a1[b], h.y, w2a[2 * j + 1]);
                        ffma2(b0[b], h.x, w2b[2 * j]);
                        ffma2(b1[b], h.y, w2b[2 * j + 1]);
                    }
                    float2 f0 = u2f2(a0[b]), f1 = u2f2(a1[b]);
                    float2 f2 = u2f2(b0[b]), f3 = u2f2(b1[b]);
                    s0[b] = (f0.x + f0.y) + (f1.x + f1.y);
                    s1[b] = (f2.x + f2.y) + (f3.x + f3.y);
                }
#pragma unroll
                for (int b = 0; b < 4; b++) {
                    s0[b] += __shfl_xor_sync(FULL, s0[b], 4);
                    s1[b] += __shfl_xor_sync(FULL, s1[b], 4);
                    s0[b] += __shfl_xor_sync(FULL, s0[b], 8);
                    s1[b] += __shfl_xor_sync(FULL, s1[b], 8);
                    s0[b] += __shfl_xor_sync(FULL, s0[b], 16);
                    s1[b] += __shfl_xor_sync(FULL, s1[b], 16);
                }
                float sel[4];
#pragma unroll
                for (int b = 0; b < 4; b++) sel[b] = rsel ? s1[b] : s0[b];
                transpose4(sel, g);
                float ai = sel[0] + b2s[0];
                float af = sel[1] + b2s[1];
                float ag = sel[2] + b2s[2];
                float ao = sel[3] + b2s[3];
                c2 = sigm(af) * c2 + sigm(ai) * tanha(ag);
                h2v = sigm(ao) * tanha(c2);
            }
            const int beta = g;
            if (i == Tlen) {
                if ((ke & 3) == 0)
                    out[(4 * cid + beta) * 64 + 16 * q + dv2] = h2v;
            } else {
                const int bufW = i & 3;
                uint32_t off = HCO + bufW * HC_BUF_BYTES +
                               (beta * 192 + 128 + 16 * q + dv2) * 4;
                st_async(rQ + off, h2v, rQ + MB2O + bufW * 8);
            }
        }
    }

    csync();  // keep smem alive for peers
}

extern "C" void kernel_launch(void* const* d_in, const int* in_sizes, int n_in,
                              void* d_out, int out_size) {
    const float* x     = (const float*)d_in[0];
    const float* w_ih1 = (const float*)d_in[1];
    const float* w_hh1 = (const float*)d_in[2];
    const float* b_ih1 = (const float*)d_in[3];
    const float* b_hh1 = (const float*)d_in[4];
    const float* w_ih2 = (const float*)d_in[5];
    const float* w_hh2 = (const float*)d_in[6];
    const float* b_ih2 = (const float*)d_in[7];
    const float* b_hh2 = (const float*)d_in[8];
    float* out = (float*)d_out;

    lstm_cluster_kernel<<<NCTA, NTHR>>>(
        x, w_ih1, w_hh1, b_ih1, b_hh1, w_ih2, w_hh2, b_ih2, b_hh2, out);
    (void)in_sizes; (void)n_in; (void)out_size;
}

// round 16
// speedup vs baseline: 2.9398x; 2.9398x over previous
#include <cuda_runtime.h>
#include <cstdint>

#define Tlen 1024
#define NCTA 128
#define NTHR 512

typedef unsigned long long ull;

#define TX1 2048   // h1: 128 dims x 4 batches x 4B per dest CTA per step
#define TX2 1024   // h2:  64 dims x 4 batches x 4B per dest CTA per step

struct __align__(16) Smem {
    ull   mb1[4];          // h1 tx-barriers, one per buffer (32 B)
    ull   mb2[4];          // h2 tx-barriers, one per buffer (32 B) -> hc at 64 B
    float hc[4][4][196];   // [buf][batch][h1(0..127) ++ h2(128..191)]
    float xs[1024][4];     // staged x, interleaved [t][b]
};
__shared__ Smem sm;

__device__ __forceinline__ float tanha(float x) {
    float y; asm("tanh.approx.f32 %0, %1;" : "=f"(y) : "f"(x)); return y;
}
__device__ __forceinline__ float sigm(float v) { return fmaf(tanha(0.5f * v), 0.5f, 0.5f); }

__device__ __forceinline__ uint32_t s2u(const void* p) {
    uint32_t a;
    asm("{ .reg .u64 t; cvta.to.shared.u64 t, %1; cvt.u32.u64 %0, t; }" : "=r"(a) : "l"(p));
    return a;
}
__device__ __forceinline__ uint32_t mapa_r(uint32_t saddr, int rank) {
    uint32_t r;
    asm volatile("mapa.shared::cluster.u32 %0, %1, %2;" : "=r"(r) : "r"(saddr), "r"(rank));
    return r;
}
__device__ __forceinline__ void st_async(uint32_t addr, float v, uint32_t mbar) {
    asm volatile(
        "st.async.shared::cluster.mbarrier::complete_tx::bytes.b32 [%0], %1, [%2];"
        :: "r"(addr), "r"(__float_as_uint(v)), "r"(mbar) : "memory");
}
__device__ __forceinline__ void arm_tx(uint32_t mbar, uint32_t bytes) {
    asm volatile("mbarrier.arrive.expect_tx.shared.b64 _, [%0], %1;"
                 :: "r"(mbar), "r"(bytes) : "memory");
}
__device__ __forceinline__ void mwait(uint32_t mbar, uint32_t parity) {
    asm volatile(
        "{\n\t.reg .pred P1;\n\t"
        "WAIT_LOOP_%=:\n\t"
        "mbarrier.try_wait.parity.acquire.cta.shared::cta.b64 P1, [%0], %1, 0x989680;\n\t"
        "@P1 bra.uni WAIT_DONE_%=;\n\t"
        "bra.uni WAIT_LOOP_%=;\n\t"
        "WAIT_DONE_%=:\n\t}"
        :: "r"(mbar), "r"(parity) : "memory");
}
__device__ __forceinline__ void csync() {
    asm volatile("barrier.cluster.arrive.aligned;" ::: "memory");
    asm volatile("barrier.cluster.wait.aligned;" ::: "memory");
}
__device__ __forceinline__ void ffma2(ull& acc, ull a, ull b) {
    asm("fma.rn.f32x2 %0, %1, %2, %0;" : "+l"(acc) : "l"(a), "l"(b));
}
__device__ __forceinline__ float2 u2f2(ull u) {
    float2 f;
    asm("mov.b64 {%0, %1}, %2;" : "=f"(f.x), "=f"(f.y) : "l"(u));
    return f;
}
__device__ __forceinline__ ull pk(float lo, float hi) {
    ull r;
    asm("mov.b64 %0, {%1, %2};" : "=l"(r) : "f"(lo), "f"(hi));
    return r;
}

// 4x4 gate<->batch transpose across lane bits [0:1]; lane G: in s[b]=M[G][b],
// out s[j]=M[j][G].
__device__ __forceinline__ void transpose4(float s[4], int G) {
    const unsigned FULL = 0xffffffffu;
    int g0 = G & 1, g1 = (G >> 1) & 1;
    float x0 = g0 ? s[0] : s[1];
    float x1 = g0 ? s[2] : s[3];
    float y0 = __shfl_xor_sync(FULL, x0, 1);
    float y1 = __shfl_xor_sync(FULL, x1, 1);
    if (g0) { s[0] = y0; s[2] = y1; } else { s[1] = y0; s[3] = y1; }
    x0 = g1 ? s[0] : s[2];
    x1 = g1 ? s[1] : s[3];
    y0 = __shfl_xor_sync(FULL, x0, 2);
    y1 = __shfl_xor_sync(FULL, x1, 2);
    if (g1) { s[0] = y0; s[1] = y1; } else { s[2] = y0; s[3] = y1; }
}

#define HC_BUF_BYTES (4 * 196 * 4)

__global__ void __launch_bounds__(NTHR, 1) __cluster_dims__(4, 1, 1)
lstm_cluster_kernel(
    const float* __restrict__ x,
    const float* __restrict__ w_ih1,  // [512][1]
    const float* __restrict__ w_hh1,  // [512][128]
    const float* __restrict__ b_ih1,
    const float* __restrict__ b_hh1,
    const float* __restrict__ w_ih2,  // [256][128]
    const float* __restrict__ w_hh2,  // [256][64]
    const float* __restrict__ b_ih2,
    const float* __restrict__ b_hh2,
    float* __restrict__ out)          // [128][64]
{
    const int tid  = threadIdx.x;
    const int lane = tid & 31;
    const int wrp  = tid >> 5;        // 16 warps: 0-7 = L1, 8-15 = L2
    const int q    = blockIdx.x & 3;
    const int cid  = blockIdx.x >> 2;
    const int g    = lane & 3;        // gate (batch after transpose)

    // ---------------- init smem ----------------
    for (int idx = tid; idx < 4 * 1024; idx += NTHR) {
        int b = idx >> 10, t = idx & 1023;
        sm.xs[t][b] = x[(4 * cid + b) * 1024 + t];
    }
    for (int idx = tid; idx < 4 * 4 * 196; idx += NTHR)
        (&sm.hc[0][0][0])[idx] = 0.0f;
    if (tid == 0) {
#pragma unroll
        for (int j = 0; j < 4; j++) {
            uint32_t a1 = s2u(&sm.mb1[j]);
            uint32_t a2 = s2u(&sm.mb2[j]);
            asm volatile("mbarrier.init.shared.b64 [%0], 1;" :: "r"(a1) : "memory");
            asm volatile("mbarrier.init.shared.b64 [%0], 1;" :: "r"(a2) : "memory");
            arm_tx(a1, TX1);
            arm_tx(a2, TX2);
        }
    }

    // ---------------- cluster address constants ----------------
    const uint32_t base0 = s2u(&sm);
    const uint32_t m0    = mapa_r(base0, 0);
    uint32_t dd[4];
    dd[0] = 0;
    dd[1] = mapa_r(base0, 1) - m0;
    dd[2] = mapa_r(base0, 2) - m0;
    dd[3] = mapa_r(base0, 3) - m0;
    const uint32_t HCO  = s2u(&sm.hc[0][0][0]) - base0;
    const uint32_t MB1O = s2u(&sm.mb1[0]) - base0;
    const uint32_t MB2O = s2u(&sm.mb2[0]) - base0;

    csync();  // armed mbars + zeroed smem + xs visible cluster-wide

    const unsigned FULL = 0xffffffffu;

    if (wrp < 8) {
        // ================= L1 warps: steps 0..Tlen-1 =================
        const int kq  = (lane >> 2) & 3;
        const int dlb = (lane >> 4) & 1;
        const int dl  = wrp * 2 + dlb;        // 0..15
        const int rsel = (kq >= 2);
        ull w1a[16], w1b[16];
        {
            const int ra = g * 128 + 32 * q + dl;
            const float* pa = w_hh1 + ra * 128 + kq * 4;
            const float* pb = w_hh1 + (ra + 16) * 128 + kq * 4;
#pragma unroll
            for (int j = 0; j < 8; j++) {
                float4 fa = *reinterpret_cast<const float4*>(pa + j * 16);
                float4 fb = *reinterpret_cast<const float4*>(pb + j * 16);
                w1a[2 * j] = pk(fa.x, fa.y); w1a[2 * j + 1] = pk(fa.z, fa.w);
                w1b[2 * j] = pk(fb.x, fb.y); w1b[2 * j + 1] = pk(fb.z, fb.w);
            }
        }
        float wih1s[4], b1s[4];
#pragma unroll
        for (int j = 0; j < 4; j++) {
            int r = j * 128 + 32 * q + dl + (rsel ? 16 : 0);
            wih1s[j] = w_ih1[r];
            b1s[j]   = b_ih1[r] + b_hh1[r];
        }
        const int dv = dl + (rsel ? 16 : 0);
        const int rep = kq & 1;               // replica -> ranks {2rep, 2rep+1}
        const uint32_t rA = m0 + dd[2 * rep];
        const uint32_t rB = m0 + dd[2 * rep + 1];

        float c1 = 0.0f;
        for (int i = 0; i < Tlen; i++) {
            // ring safety FIRST: fast path, almost always already complete
            if (i >= 4) {
                const int s = i - 3;
                mwait(base0 + MB2O + (s & 3) * 8, (uint32_t)((s >> 2) & 1));
            }
            int bufR = 3;                     // zeroed buffer for i==0
            if (i >= 1) {
                const int s = i - 1;
                bufR = s & 3;
                mwait(base0 + MB1O + bufR * 8, (uint32_t)((s >> 2) & 1));
                if (tid == 0)
                    arm_tx(base0 + MB1O + bufR * 8, TX1);  // re-arm next phase
            }
            float s0[4], s1[4];
#pragma unroll
            for (int b = 0; b < 4; b++) {
                const ulonglong2* hp =
                    reinterpret_cast<const ulonglong2*>(&sm.hc[bufR][b][0]);
                ull a0 = 0ull, a1 = 0ull, b0 = 0ull, b1 = 0ull;
#pragma unroll
                for (int j = 0; j < 8; j++) {
                    ulonglong2 h = hp[kq + 4 * j];   // 4 distinct addrs/warp
                    ffma2(a0, h.x, w1a[2 * j]);
                    ffma2(a1, h.y, w1a[2 * j + 1]);
                    ffma2(b0, h.x, w1b[2 * j]);
                    ffma2(b1, h.y, w1b[2 * j + 1]);
                }
                float2 f0 = u2f2(a0), f1 = u2f2(a1);
                float2 f2 = u2f2(b0), f3 = u2f2(b1);
                s0[b] = (f0.x + f0.y) + (f1.x + f1.y);
                s1[b] = (f2.x + f2.y) + (f3.x + f3.y);
            }
#pragma unroll
            for (int b = 0; b < 4; b++) {
                s0[b] += __shfl_xor_sync(FULL, s0[b], 4);
                s1[b] += __shfl_xor_sync(FULL, s1[b], 4);
                s0[b] += __shfl_xor_sync(FULL, s0[b], 8);
                s1[b] += __shfl_xor_sync(FULL, s1[b], 8);
            }
            float sel[4];
#pragma unroll
            for (int b = 0; b < 4; b++) sel[b] = rsel ? s1[b] : s0[b];
            transpose4(sel, g);
            const int beta = g;
            float xv = sm.xs[i][beta];
            float ai = fmaf(xv, wih1s[0], sel[0] + b1s[0]);
            float af = fmaf(xv, wih1s[1], sel[1] + b1s[1]);
            float ag = fmaf(xv, wih1s[2], sel[2] + b1s[2]);
            float ao = fmaf(xv, wih1s[3], sel[3] + b1s[3]);
            c1 = sigm(af) * c1 + sigm(ai) * tanha(ag);
            float h = sigm(ao) * tanha(c1);
            const int bufW = i & 3;
            uint32_t off  = HCO + bufW * HC_BUF_BYTES + (beta * 196 + 32 * q + dv) * 4;
            uint32_t mbof = MB1O + bufW * 8;
            st_async(rA + off, h, rA + mbof);
            st_async(rB + off, h, rB + mbof);
        }
    } else {
        // ================= L2 warps: steps 0..Tlen =================
        const int ke  = lane >> 2;            // 0..7
        const int dl2 = wrp - 8;              // 0..7
        const int rsel = (ke >= 4);
        ull w2a[12], w2b[12];
        {
            const int ra = g * 64 + 16 * q + dl2;
            const int rb = ra + 8;
#pragma unroll
            for (int j = 0; j < 6; j++) {
                int k0 = ke * 4 + 32 * j;     // 4-float chunk, never straddles 128
                float4 fa, fb;
                if (k0 < 128) {
                    fa = *reinterpret_cast<const float4*>(w_ih2 + ra * 128 + k0);
                    fb = *reinterpret_cast<const float4*>(w_ih2 + rb * 128 + k0);
                } else {
                    fa = *reinterpret_cast<const float4*>(w_hh2 + ra * 64 + (k0 - 128));
                    fb = *reinterpret_cast<const float4*>(w_hh2 + rb * 64 + (k0 - 128));
                }
                w2a[2 * j] = pk(fa.x, fa.y); w2a[2 * j + 1] = pk(fa.z, fa.w);
                w2b[2 * j] = pk(fb.x, fb.y); w2b[2 * j + 1] = pk(fb.z, fb.w);
            }
        }
        float b2s[4];
#pragma unroll
        for (int j = 0; j < 4; j++) {
            int r = j * 64 + 16 * q + dl2 + (rsel ? 8 : 0);
            b2s[j] = b_ih2[r] + b_hh2[r];
        }
        const int dv2 = dl2 + (rsel ? 8 : 0);
        const uint32_t rQ = m0 + dd[ke & 3];  // 1 store/lane covers 4 ranks/row

        float c2 = 0.0f;
        for (int i = 0; i <= Tlen; i++) {
            float h2v = 0.0f;
            if (i >= 1) {
                const int s = i - 1;
                const int bufR = s & 3;
                const uint32_t par = (uint32_t)((s >> 2) & 1);
                // 1) old h2 first (almost always complete)
                mwait(base0 + MB2O + bufR * 8, par);
                if (tid == 256)
                    arm_tx(base0 + MB2O + bufR * 8, TX2);
                const ulonglong2* hp0 =
                    reinterpret_cast<const ulonglong2*>(&sm.hc[bufR][0][0]);
                // 2) h2-part dot (j=4,5) while h1 may still be in flight
                ull a0[4], a1[4], b0[4], b1[4];
#pragma unroll
                for (int b = 0; b < 4; b++) {
                    const ulonglong2* hp = hp0 + b * 49;   // 196 floats = 49 ull2
                    a0[b] = a1[b] = b0[b] = b1[b] = 0ull;
#pragma unroll
                    for (int j = 4; j < 6; j++) {
                        ulonglong2 h = hp[ke + 8 * j];
                        ffma2(a0[b], h.x, w2a[2 * j]);
                        ffma2(a1[b], h.y, w2a[2 * j + 1]);
                        ffma2(b0[b], h.x, w2b[2 * j]);
                        ffma2(b1[b], h.y, w2b[2 * j + 1]);
                    }
                }
                // 3) fresh h1, then remaining dot
                mwait(base0 + MB1O + bufR * 8, par);
                float s0[4], s1[4];
#pragma unroll
                for (int b = 0; b < 4; b++) {
                    const ulonglong2* hp = hp0 + b * 49;
#pragma unroll
                    for (int j = 0; j < 4; j++) {
                        ulonglong2 h = hp[ke + 8 * j];
                        ffma2(a0[b], h.x, w2a[2 * j]);
                        ffma2(a1[b], h.y, w2a[2 * j + 1]);
                        ffma2(b0[b], h.x, w2b[2 * j]);
                        ffma2(b1[b], h.y, w2b[2 * j + 1]);
                    }
                    float2 f0 = u2f2(a0[b]), f1 = u2f2(a1[b]);
                    float2 f2 = u2f2(b0[b]), f3 = u2f2(b1[b]);
                    s0[b] = (f0.x + f0.y) + (f1.x + f1.y);
                    s1[b] = (f2.x + f2.y) + (f3.x + f3.y);
                }
#pragma unroll
                for (int b = 0; b < 4; b++) {
                    s0[b] += __shfl_xor_sync(FULL, s0[b], 4);
                    s1[b] += __shfl_xor_sync(FULL, s1[b], 4);
                    s0[b] += __shfl_xor_sync(FULL, s0[b], 8);
                    s1[b] += __shfl_xor_sync(FULL, s1[b], 8);
                    s0[b] += __shfl_xor_sync(FULL, s0[b], 16);
                    s1[b] += __shfl_xor_sync(FULL, s1[b], 16);
                }
                float sel[4];
#pragma unroll
                for (int b = 0; b < 4; b++) sel[b] = rsel ? s1[b] : s0[b];
                transpose4(sel, g);
                float ai = sel[0] + b2s[0];
                float af = sel[1] + b2s[1];
                float ag = sel[2] + b2s[2];
                float ao = sel[3] + b2s[3];
                c2 = sigm(af) * c2 + sigm(ai) * tanha(ag);
                h2v = sigm(ao) * tanha(c2);
            }
            const int beta = g;
            if (i == Tlen) {
                if ((ke & 3) == 0)
                    out[(4 * cid + beta) * 64 + 16 * q + dv2] = h2v;
            } else {
                const int bufW = i & 3;
                uint32_t off = HCO + bufW * HC_BUF_BYTES +
                               (beta * 196 + 128 + 16 * q + dv2) * 4;
                st_async(rQ + off, h2v, rQ + MB2O + bufW * 8);
            }
        }
    }

    csync();  // keep smem alive for peers
}

extern "C" void kernel_launch(void* const* d_in, const int* in_sizes, int n_in,
                              void* d_out, int out_size) {
    const float* x     = (const float*)d_in[0];
    const float* w_ih1 = (const float*)d_in[1];
    const float* w_hh1 = (const float*)d_in[2];
    const float* b_ih1 = (const float*)d_in[3];
    const float* b_hh1 = (const float*)d_in[4];
    const float* w_ih2 = (const float*)d_in[5];
    const float* w_hh2 = (const float*)d_in[6];
    const float* b_ih2 = (const float*)d_in[7];
    const float* b_hh2 = (const float*)d_in[8];
    float* out = (float*)d_out;

    lstm_cluster_kernel<<<NCTA, NTHR>>>(
        x, w_ih1, w_hh1, b_ih1, b_hh1, w_ih2, w_hh2, b_ih2, b_hh2, out);
    (void)in_sizes; (void)n_in; (void)out_size;
}